// round 1
// baseline (speedup 1.0000x reference)
#include <cuda_runtime.h>
#include <cuda_bf16.h>

// Problem constants (fixed by the reference)
#define Nn 50000
#define Ne 800000
// IN=128, H1=8, HID=32, OUT=64

// ---------------- device scratch (static allocation, allowed) ----------------
__device__ float g_h1[(size_t)Nn * 256];   // layer1 projected features [N,8,32]
__device__ float g_x1[(size_t)Nn * 256];   // layer1 output (relu) = layer2 input
__device__ float g_el1[Nn * 8], g_er1[Nn * 8];
__device__ float g_h2[(size_t)Nn * 32];
__device__ float g_el2[Nn], g_er2[Nn];
__device__ float g_h3[(size_t)Nn * 64];
__device__ float g_el3[Nn], g_er3[Nn];

__device__ int g_deg[Nn];
__device__ int g_fill[Nn];
__device__ int g_rowstart[Nn + 1];
__device__ int g_esrc[Ne];                 // src indices sorted (bucketed) by dst

// ---------------- helpers ----------------
__device__ __forceinline__ float wred(float v) {
#pragma unroll
    for (int o = 16; o > 0; o >>= 1) v += __shfl_xor_sync(0xffffffffu, v, o);
    return v;
}

__device__ __forceinline__ float lrelu(float x) {
    return x > 0.f ? x : 0.2f * x;
}

// ---------------- CSR build ----------------
__global__ void zero_kernel() {
    int i = blockIdx.x * blockDim.x + threadIdx.x;
    if (i < Nn) { g_deg[i] = 0; g_fill[i] = 0; }
}

__global__ void count_kernel(const int* __restrict__ dst) {
    int e = blockIdx.x * blockDim.x + threadIdx.x;
    if (e < Ne) atomicAdd(&g_deg[dst[e]], 1);
}

// single-block hierarchical exclusive scan of g_deg -> g_rowstart
__global__ void scan_kernel() {
    __shared__ int warpsum[32];
    const int t = threadIdx.x;            // 1024 threads
    const int lane = t & 31, wid = t >> 5;
    const int CH = (Nn + 1023) / 1024;    // 49
    const int base = t * CH;
    int sum = 0;
#pragma unroll 1
    for (int i = 0; i < CH; i++) {
        int idx = base + i;
        if (idx < Nn) sum += g_deg[idx];
    }
    // inclusive scan within warp
    int v = sum;
#pragma unroll
    for (int o = 1; o < 32; o <<= 1) {
        int u = __shfl_up_sync(0xffffffffu, v, o);
        if (lane >= o) v += u;
    }
    if (lane == 31) warpsum[wid] = v;
    __syncthreads();
    if (wid == 0) {
        int w = warpsum[lane];
        int vv = w;
#pragma unroll
        for (int o = 1; o < 32; o <<= 1) {
            int u = __shfl_up_sync(0xffffffffu, vv, o);
            if (lane >= o) vv += u;
        }
        warpsum[lane] = vv;
    }
    __syncthreads();
    int excl = v - sum + (wid > 0 ? warpsum[wid - 1] : 0);
    int run = excl;
#pragma unroll 1
    for (int i = 0; i < CH; i++) {
        int idx = base + i;
        if (idx < Nn) { g_rowstart[idx] = run; run += g_deg[idx]; }
    }
    if (t == 1023) g_rowstart[Nn] = run;  // last chunk empty -> run == E
}

__global__ void scatter_kernel(const int* __restrict__ src, const int* __restrict__ dst) {
    int e = blockIdx.x * blockDim.x + threadIdx.x;
    if (e >= Ne) return;
    int d = dst[e];
    int pos = g_rowstart[d] + atomicAdd(&g_fill[d], 1);
    g_esrc[pos] = src[e];
}

// ---------------- layer 1: GEMM [N,128]@[128,256] + el/er ----------------
__global__ void gemm1_kernel(const float* __restrict__ X, const float* __restrict__ W,
                             const float* __restrict__ al, const float* __restrict__ ar) {
    __shared__ float xs[128 * 8];   // transposed: xs[k*8 + i]
    const int c = threadIdx.x;      // 256 threads = output column
    const int n0 = blockIdx.x * 8;
#pragma unroll
    for (int r = 0; r < 4; r++) {
        int idx = c + 256 * r;
        int i = idx >> 7, k = idx & 127;
        xs[k * 8 + i] = X[(size_t)(n0 + i) * 128 + k];
    }
    __syncthreads();
    float acc[8] = {0, 0, 0, 0, 0, 0, 0, 0};
    const float* Wc = W + c;
#pragma unroll 4
    for (int k = 0; k < 128; k++) {
        float w = __ldg(&Wc[k * 256]);
        float4 a = *reinterpret_cast<const float4*>(&xs[k * 8]);
        float4 b = *reinterpret_cast<const float4*>(&xs[k * 8 + 4]);
        acc[0] = fmaf(a.x, w, acc[0]);
        acc[1] = fmaf(a.y, w, acc[1]);
        acc[2] = fmaf(a.z, w, acc[2]);
        acc[3] = fmaf(a.w, w, acc[3]);
        acc[4] = fmaf(b.x, w, acc[4]);
        acc[5] = fmaf(b.y, w, acc[5]);
        acc[6] = fmaf(b.z, w, acc[6]);
        acc[7] = fmaf(b.w, w, acc[7]);
    }
    const float av = al[c], rv = ar[c];
    const int w8 = c >> 5, lane = c & 31;
#pragma unroll
    for (int i = 0; i < 8; i++) {
        g_h1[(size_t)(n0 + i) * 256 + c] = acc[i];
        float e = wred(acc[i] * av);
        float r = wred(acc[i] * rv);
        if (lane == 0) {
            g_el1[(n0 + i) * 8 + w8] = e;
            g_er1[(n0 + i) * 8 + w8] = r;
        }
    }
}

// ---------------- layer 1 aggregation: warp per dst, 8 heads x 32 feat ----------------
__global__ void agg1_kernel(const float* __restrict__ b1) {
    const int wid = (blockIdx.x * blockDim.x + threadIdx.x) >> 5;
    const int lane = threadIdx.x & 31;
    if (wid >= Nn) return;
    const int d = wid;
    const int rs = g_rowstart[d], re = g_rowstart[d + 1];
    const float erh = (lane < 8) ? g_er1[d * 8 + lane] : 0.f;
    float acc[8] = {0, 0, 0, 0, 0, 0, 0, 0};
    float s = 0.f;
    for (int e = rs; e < re; e++) {
        int src = g_esrc[e];
        float ee = 0.f;
        if (lane < 8) {
            float lg = lrelu(g_el1[src * 8 + lane] + erh);
            ee = __expf(lg);
            s += ee;
        }
        const float* hp = g_h1 + (size_t)src * 256;
#pragma unroll
        for (int h = 0; h < 8; h++) {
            float eh = __shfl_sync(0xffffffffu, ee, h);
            acc[h] = fmaf(eh, hp[h * 32 + lane], acc[h]);
        }
    }
#pragma unroll
    for (int h = 0; h < 8; h++) {
        float sh = __shfl_sync(0xffffffffu, s, h);
        float v = (sh > 0.f) ? acc[h] / sh : 0.f;
        v += b1[h * 32 + lane];
        g_x1[(size_t)d * 256 + h * 32 + lane] = fmaxf(v, 0.f);  // relu
    }
}

// ---------------- layer 2: GEMM [N,256]@[256,32] + el/er ----------------
__global__ void gemm2_kernel(const float* __restrict__ W,
                             const float* __restrict__ al, const float* __restrict__ ar) {
    __shared__ float xs[8 * 256];
    const int t = threadIdx.x;      // 256
    const int n0 = blockIdx.x * 8;
#pragma unroll
    for (int r = 0; r < 8; r++) xs[t + 256 * r] = g_x1[(size_t)n0 * 256 + t + 256 * r];
    __syncthreads();
    const int i = t >> 5, c = t & 31;
    const float* xr = xs + i * 256;
    float acc = 0.f;
#pragma unroll 8
    for (int k = 0; k < 256; k++) acc = fmaf(xr[k], __ldg(&W[k * 32 + c]), acc);
    const int n = n0 + i;
    g_h2[(size_t)n * 32 + c] = acc;
    float e = wred(acc * al[c]);
    float r = wred(acc * ar[c]);
    if (c == 0) { g_el2[n] = e; g_er2[n] = r; }
}

// ---------------- layer 2 aggregation: warp per dst, 1 head x 32 feat ----------------
__global__ void agg2_kernel(const float* __restrict__ b2, float* __restrict__ emb) {
    const int wid = (blockIdx.x * blockDim.x + threadIdx.x) >> 5;
    const int lane = threadIdx.x & 31;
    if (wid >= Nn) return;
    const int d = wid;
    const int rs = g_rowstart[d], re = g_rowstart[d + 1];
    const float erd = g_er2[d];
    float acc = 0.f, s = 0.f;
    for (int e = rs; e < re; e++) {
        int src = g_esrc[e];
        float ee = __expf(lrelu(g_el2[src] + erd));
        s += ee;
        acc = fmaf(ee, g_h2[(size_t)src * 32 + lane], acc);
    }
    float v = (s > 0.f) ? acc / s : 0.f;
    emb[(size_t)d * 32 + lane] = v + b2[lane];
}

// ---------------- layer 3: GEMM [N,32]@[32,64] + el/er ----------------
__global__ void gemm3_kernel(const float* __restrict__ X, const float* __restrict__ W,
                             const float* __restrict__ al, const float* __restrict__ ar) {
    __shared__ float xs[4 * 32];
    __shared__ float sm_e[8], sm_r[8];
    const int t = threadIdx.x;      // 256
    const int n0 = blockIdx.x * 4;
    if (t < 128) xs[t] = X[(size_t)n0 * 32 + t];
    __syncthreads();
    const int i = t >> 6, c = t & 63;
    float acc = 0.f;
#pragma unroll
    for (int k = 0; k < 32; k++) acc = fmaf(xs[i * 32 + k], __ldg(&W[k * 64 + c]), acc);
    const int n = n0 + i;
    g_h3[(size_t)n * 64 + c] = acc;
    float e = wred(acc * al[c]);
    float r = wred(acc * ar[c]);
    const int warp = t >> 5, lane = t & 31;
    if (lane == 0) { sm_e[warp] = e; sm_r[warp] = r; }
    __syncthreads();
    if (t < 4) {
        g_el3[n0 + t] = sm_e[2 * t] + sm_e[2 * t + 1];
        g_er3[n0 + t] = sm_r[2 * t] + sm_r[2 * t + 1];
    }
}

// ---------------- layer 3 aggregation: warp per dst, 1 head x 64 feat ----------------
__global__ void agg3_kernel(const float* __restrict__ b3, float* __restrict__ out) {
    const int wid = (blockIdx.x * blockDim.x + threadIdx.x) >> 5;
    const int lane = threadIdx.x & 31;
    if (wid >= Nn) return;
    const int d = wid;
    const int rs = g_rowstart[d], re = g_rowstart[d + 1];
    const float erd = g_er3[d];
    float acc0 = 0.f, acc1 = 0.f, s = 0.f;
    for (int e = rs; e < re; e++) {
        int src = g_esrc[e];
        float ee = __expf(lrelu(g_el3[src] + erd));
        s += ee;
        const float* hp = g_h3 + (size_t)src * 64;
        acc0 = fmaf(ee, hp[lane], acc0);
        acc1 = fmaf(ee, hp[32 + lane], acc1);
    }
    float inv = (s > 0.f) ? (1.f / s) : 0.f;
    out[(size_t)d * 64 + lane]      = acc0 * inv + b3[lane];
    out[(size_t)d * 64 + 32 + lane] = acc1 * inv + b3[32 + lane];
}

// ---------------- launch ----------------
extern "C" void kernel_launch(void* const* d_in, const int* in_sizes, int n_in,
                              void* d_out, int out_size) {
    const float* features = (const float*)d_in[0];
    const int*   src      = (const int*)d_in[1];
    const int*   dst      = (const int*)d_in[2];
    const float* W1  = (const float*)d_in[3];
    const float* al1 = (const float*)d_in[4];
    const float* ar1 = (const float*)d_in[5];
    const float* b1  = (const float*)d_in[6];
    const float* W2  = (const float*)d_in[7];
    const float* al2 = (const float*)d_in[8];
    const float* ar2 = (const float*)d_in[9];
    const float* b2  = (const float*)d_in[10];
    const float* W3  = (const float*)d_in[11];
    const float* al3 = (const float*)d_in[12];
    const float* ar3 = (const float*)d_in[13];
    const float* b3  = (const float*)d_in[14];

    float* out = (float*)d_out;                 // h: [N,64] first
    float* emb = out + (size_t)Nn * 64;         // embedding: [N,32] second

    // CSR build (graph identical across layers)
    zero_kernel<<<(Nn + 255) / 256, 256>>>();
    count_kernel<<<(Ne + 255) / 256, 256>>>(dst);
    scan_kernel<<<1, 1024>>>();
    scatter_kernel<<<(Ne + 255) / 256, 256>>>(src, dst);

    // layer 1
    gemm1_kernel<<<Nn / 8, 256>>>(features, W1, al1, ar1);
    agg1_kernel<<<Nn / 8, 256>>>(b1);
    // layer 2
    gemm2_kernel<<<Nn / 8, 256>>>(W2, al2, ar2);
    agg2_kernel<<<Nn / 8, 256>>>(b2, emb);
    // layer 3
    gemm3_kernel<<<Nn / 4, 256>>>(emb, W3, al3, ar3);
    agg3_kernel<<<Nn / 8, 256>>>(b3, out);
}

// round 2
// speedup vs baseline: 1.1730x; 1.1730x over previous
#include <cuda_runtime.h>
#include <cuda_bf16.h>

// Problem constants (fixed by the reference)
#define Nn 50000
#define Ne 800000
// IN=128, H1=8, HID=32, OUT=64

// ---------------- device scratch (static allocation, allowed) ----------------
__device__ float g_h1[(size_t)Nn * 256];   // layer1 projected features [N,8,32]
__device__ float g_x1[(size_t)Nn * 256];   // layer1 output (relu) = layer2 input
__device__ float g_el1[Nn * 8], g_er1[Nn * 8];
__device__ float g_h2[(size_t)Nn * 32];
__device__ float g_el2[Nn], g_er2[Nn];
__device__ float g_h3[(size_t)Nn * 64];
__device__ float g_el3[Nn], g_er3[Nn];

__device__ int g_deg[Nn];
__device__ int g_fill[Nn];
__device__ int g_rowstart[Nn + 1];
__device__ int g_esrc[Ne];                 // src indices sorted (bucketed) by dst

__device__ unsigned g_wpk[128 * 256];      // W1 packed bf16 (lo16=hi part, hi16=lo part)

// ---------------- helpers ----------------
__device__ __forceinline__ float wred(float v) {
#pragma unroll
    for (int o = 16; o > 0; o >>= 1) v += __shfl_xor_sync(0xffffffffu, v, o);
    return v;
}

__device__ __forceinline__ float lrelu(float x) {
    return x > 0.f ? x : 0.2f * x;
}

__device__ __forceinline__ void mma16816(float c[4], unsigned a0, unsigned a1,
                                         unsigned a2, unsigned a3,
                                         unsigned b0, unsigned b1) {
    asm volatile(
        "mma.sync.aligned.m16n8k16.row.col.f32.bf16.bf16.f32 "
        "{%0,%1,%2,%3}, {%4,%5,%6,%7}, {%8,%9}, {%0,%1,%2,%3};\n"
        : "+f"(c[0]), "+f"(c[1]), "+f"(c[2]), "+f"(c[3])
        : "r"(a0), "r"(a1), "r"(a2), "r"(a3), "r"(b0), "r"(b1));
}

// ---------------- CSR build ----------------
__global__ void zero_kernel() {
    int i = blockIdx.x * blockDim.x + threadIdx.x;
    if (i < Nn) { g_deg[i] = 0; g_fill[i] = 0; }
}

__global__ void count_kernel(const int* __restrict__ dst) {
    int e = blockIdx.x * blockDim.x + threadIdx.x;
    if (e < Ne) atomicAdd(&g_deg[dst[e]], 1);
}

// single-block hierarchical exclusive scan of g_deg -> g_rowstart
__global__ void scan_kernel() {
    __shared__ int warpsum[32];
    const int t = threadIdx.x;            // 1024 threads
    const int lane = t & 31, wid = t >> 5;
    const int CH = (Nn + 1023) / 1024;    // 49
    const int base = t * CH;
    int sum = 0;
#pragma unroll 1
    for (int i = 0; i < CH; i++) {
        int idx = base + i;
        if (idx < Nn) sum += g_deg[idx];
    }
    int v = sum;
#pragma unroll
    for (int o = 1; o < 32; o <<= 1) {
        int u = __shfl_up_sync(0xffffffffu, v, o);
        if (lane >= o) v += u;
    }
    if (lane == 31) warpsum[wid] = v;
    __syncthreads();
    if (wid == 0) {
        int w = warpsum[lane];
        int vv = w;
#pragma unroll
        for (int o = 1; o < 32; o <<= 1) {
            int u = __shfl_up_sync(0xffffffffu, vv, o);
            if (lane >= o) vv += u;
        }
        warpsum[lane] = vv;
    }
    __syncthreads();
    int excl = v - sum + (wid > 0 ? warpsum[wid - 1] : 0);
    int run = excl;
#pragma unroll 1
    for (int i = 0; i < CH; i++) {
        int idx = base + i;
        if (idx < Nn) { g_rowstart[idx] = run; run += g_deg[idx]; }
    }
    if (t == 1023) g_rowstart[Nn] = run;
}

__global__ void scatter_kernel(const int* __restrict__ src, const int* __restrict__ dst) {
    int e = blockIdx.x * blockDim.x + threadIdx.x;
    if (e >= Ne) return;
    int d = dst[e];
    int pos = g_rowstart[d] + atomicAdd(&g_fill[d], 1);
    g_esrc[pos] = src[e];
}

// ---------------- W1 bf16 hi/lo packing ----------------
__global__ void wpack_kernel(const float* __restrict__ W) {
    int i = blockIdx.x * blockDim.x + threadIdx.x;   // 32768
    float w = W[i];
    __nv_bfloat16 h = __float2bfloat16(w);
    float hf = __bfloat162float(h);
    __nv_bfloat16 l = __float2bfloat16(w - hf);
    unsigned hb = __bfloat16_as_ushort(h);
    unsigned lb = __bfloat16_as_ushort(l);
    g_wpk[i] = hb | (lb << 16);                       // phys k even = hi, odd = lo
}

// ---------------- layer 1 GEMM via bf16 split-product tensor cores --------
// C[64, 256] per block = X[64,128] @ W[128,256], fp32-accurate (2-pass split).
#define A_STRIDE 132
#define B_STRIDE 264
#define G1_SMEM ((2 * 64 * A_STRIDE + 128 * B_STRIDE) * 4)

__global__ void __launch_bounds__(256) gemm1m_kernel(const float* __restrict__ X) {
    extern __shared__ unsigned smem[];
    unsigned* A1 = smem;                        // (ah, ah) packed, [64][128] pad 132
    unsigned* A2 = smem + 64 * A_STRIDE;        // (al, al) packed
    unsigned* B  = smem + 2 * 64 * A_STRIDE;    // (bh, bl) packed, [128][256] pad 264

    const int t = threadIdx.x;
    const int n0 = blockIdx.x * 64;

    // load & split-pack A tile (64 rows x 128 k fp32)
#pragma unroll
    for (int i = 0; i < 8; i++) {
        int idx = t + 256 * i;                  // float4 index, 2048 total
        int row = idx >> 5, c4 = idx & 31;
        int grow = n0 + row;
        float4 v = (grow < Nn) ? __ldg((const float4*)(X + (size_t)grow * 128) + c4)
                               : make_float4(0.f, 0.f, 0.f, 0.f);
        float vv[4] = {v.x, v.y, v.z, v.w};
        unsigned p1[4], p2[4];
#pragma unroll
        for (int j = 0; j < 4; j++) {
            __nv_bfloat16 h = __float2bfloat16(vv[j]);
            float hf = __bfloat162float(h);
            __nv_bfloat16 l = __float2bfloat16(vv[j] - hf);
            unsigned hb = __bfloat16_as_ushort(h);
            unsigned lb = __bfloat16_as_ushort(l);
            p1[j] = hb | (hb << 16);
            p2[j] = lb | (lb << 16);
        }
        *(uint4*)&A1[row * A_STRIDE + c4 * 4] = make_uint4(p1[0], p1[1], p1[2], p1[3]);
        *(uint4*)&A2[row * A_STRIDE + c4 * 4] = make_uint4(p2[0], p2[1], p2[2], p2[3]);
    }
    // load B (pre-packed W1): 128x256 u32
#pragma unroll
    for (int i = 0; i < 32; i++) {
        int idx = t + 256 * i;                  // uint4 index, 8192 total
        int row = idx >> 6, c4 = idx & 63;
        uint4 v = *((const uint4*)g_wpk + idx);
        *(uint4*)&B[row * B_STRIDE + c4 * 4] = v;
    }
    __syncthreads();

    const int warp = t >> 5, lane = t & 31;
    const int wm = warp >> 2, wn = warp & 3;    // 2 (M) x 4 (N) warps
    const int g = lane >> 2, tr = lane & 3;

    float c[2][8][4] = {};
#pragma unroll 1
    for (int ks = 0; ks < 16; ks++) {
        int kb = ks * 8;                        // logical k base
        unsigned b0[8], b1[8];
#pragma unroll
        for (int nt = 0; nt < 8; nt++) {
            int col = wn * 64 + nt * 8 + g;
            b0[nt] = B[(kb + tr) * B_STRIDE + col];
            b1[nt] = B[(kb + 4 + tr) * B_STRIDE + col];
        }
#pragma unroll
        for (int pass = 0; pass < 2; pass++) {
            const unsigned* Ap = pass ? A2 : A1;
#pragma unroll
            for (int mt = 0; mt < 2; mt++) {
                int rb = wm * 32 + mt * 16;
                unsigned a0 = Ap[(rb + g) * A_STRIDE + kb + tr];
                unsigned a1 = Ap[(rb + 8 + g) * A_STRIDE + kb + tr];
                unsigned a2 = Ap[(rb + g) * A_STRIDE + kb + 4 + tr];
                unsigned a3 = Ap[(rb + 8 + g) * A_STRIDE + kb + 4 + tr];
#pragma unroll
                for (int nt = 0; nt < 8; nt++)
                    mma16816(c[mt][nt], a0, a1, a2, a3, b0[nt], b1[nt]);
            }
        }
    }

    // store C
#pragma unroll
    for (int mt = 0; mt < 2; mt++) {
        int r0 = n0 + wm * 32 + mt * 16 + g;
#pragma unroll
        for (int nt = 0; nt < 8; nt++) {
            int col = wn * 64 + nt * 8 + tr * 2;
            if (r0 < Nn)
                *(float2*)&g_h1[(size_t)r0 * 256 + col] = make_float2(c[mt][nt][0], c[mt][nt][1]);
            if (r0 + 8 < Nn)
                *(float2*)&g_h1[(size_t)(r0 + 8) * 256 + col] = make_float2(c[mt][nt][2], c[mt][nt][3]);
        }
    }
}

// ---------------- layer 1 el/er: warp per node over g_h1 ----------------
__global__ void elr1_kernel(const float* __restrict__ al, const float* __restrict__ ar) {
    const int wid = (blockIdx.x * blockDim.x + threadIdx.x) >> 5;
    const int lane = threadIdx.x & 31;
    if (wid >= Nn) return;
    const float4* hp = (const float4*)(g_h1 + (size_t)wid * 256);
    float4 h0 = hp[lane * 2], h1 = hp[lane * 2 + 1];
    float4 a0 = __ldg((const float4*)al + lane * 2);
    float4 a1 = __ldg((const float4*)al + lane * 2 + 1);
    float4 r0 = __ldg((const float4*)ar + lane * 2);
    float4 r1 = __ldg((const float4*)ar + lane * 2 + 1);
    float e = h0.x * a0.x + h0.y * a0.y + h0.z * a0.z + h0.w * a0.w
            + h1.x * a1.x + h1.y * a1.y + h1.z * a1.z + h1.w * a1.w;
    float r = h0.x * r0.x + h0.y * r0.y + h0.z * r0.z + h0.w * r0.w
            + h1.x * r1.x + h1.y * r1.y + h1.z * r1.z + h1.w * r1.w;
    e += __shfl_xor_sync(0xffffffffu, e, 1);
    e += __shfl_xor_sync(0xffffffffu, e, 2);
    r += __shfl_xor_sync(0xffffffffu, r, 1);
    r += __shfl_xor_sync(0xffffffffu, r, 2);
    if ((lane & 3) == 0) {
        g_el1[wid * 8 + (lane >> 2)] = e;
        g_er1[wid * 8 + (lane >> 2)] = r;
    }
}

// ---------------- layer 1 aggregation: warp per dst, 8 heads x 32 feat ----
__global__ void agg1_kernel(const float* __restrict__ b1) {
    const int wid = (blockIdx.x * blockDim.x + threadIdx.x) >> 5;
    const int lane = threadIdx.x & 31;
    if (wid >= Nn) return;
    const int d = wid;
    const int rs = g_rowstart[d], re = g_rowstart[d + 1];
    const float erh = (lane < 8) ? g_er1[d * 8 + lane] : 0.f;
    float acc[8] = {0, 0, 0, 0, 0, 0, 0, 0};
    float s = 0.f;
    for (int e = rs; e < re; e++) {
        int src = g_esrc[e];
        float ee = 0.f;
        if (lane < 8) {
            float lg = lrelu(g_el1[src * 8 + lane] + erh);
            ee = __expf(lg);
            s += ee;
        }
        const float* hp = g_h1 + (size_t)src * 256;
#pragma unroll
        for (int h = 0; h < 8; h++) {
            float eh = __shfl_sync(0xffffffffu, ee, h);
            acc[h] = fmaf(eh, hp[h * 32 + lane], acc[h]);
        }
    }
#pragma unroll
    for (int h = 0; h < 8; h++) {
        float sh = __shfl_sync(0xffffffffu, s, h);
        float v = (sh > 0.f) ? acc[h] / sh : 0.f;
        v += b1[h * 32 + lane];
        g_x1[(size_t)d * 256 + h * 32 + lane] = fmaxf(v, 0.f);  // relu
    }
}

// ---------------- layer 2: GEMM [N,256]@[256,32] + el/er ----------------
__global__ void gemm2_kernel(const float* __restrict__ W,
                             const float* __restrict__ al, const float* __restrict__ ar) {
    __shared__ float xs[8 * 256];
    const int t = threadIdx.x;      // 256
    const int n0 = blockIdx.x * 8;
#pragma unroll
    for (int r = 0; r < 8; r++) xs[t + 256 * r] = g_x1[(size_t)n0 * 256 + t + 256 * r];
    __syncthreads();
    const int i = t >> 5, c = t & 31;
    const float* xr = xs + i * 256;
    float acc = 0.f;
#pragma unroll 8
    for (int k = 0; k < 256; k++) acc = fmaf(xr[k], __ldg(&W[k * 32 + c]), acc);
    const int n = n0 + i;
    g_h2[(size_t)n * 32 + c] = acc;
    float e = wred(acc * al[c]);
    float r = wred(acc * ar[c]);
    if (c == 0) { g_el2[n] = e; g_er2[n] = r; }
}

// ---------------- layer 2 aggregation ----------------
__global__ void agg2_kernel(const float* __restrict__ b2, float* __restrict__ emb) {
    const int wid = (blockIdx.x * blockDim.x + threadIdx.x) >> 5;
    const int lane = threadIdx.x & 31;
    if (wid >= Nn) return;
    const int d = wid;
    const int rs = g_rowstart[d], re = g_rowstart[d + 1];
    const float erd = g_er2[d];
    float acc = 0.f, s = 0.f;
    for (int e = rs; e < re; e++) {
        int src = g_esrc[e];
        float ee = __expf(lrelu(g_el2[src] + erd));
        s += ee;
        acc = fmaf(ee, g_h2[(size_t)src * 32 + lane], acc);
    }
    float v = (s > 0.f) ? acc / s : 0.f;
    emb[(size_t)d * 32 + lane] = v + b2[lane];
}

// ---------------- layer 3: GEMM [N,32]@[32,64] + el/er ----------------
__global__ void gemm3_kernel(const float* __restrict__ X, const float* __restrict__ W,
                             const float* __restrict__ al, const float* __restrict__ ar) {
    __shared__ float xs[4 * 32];
    __shared__ float sm_e[8], sm_r[8];
    const int t = threadIdx.x;      // 256
    const int n0 = blockIdx.x * 4;
    if (t < 128) xs[t] = X[(size_t)n0 * 32 + t];
    __syncthreads();
    const int i = t >> 6, c = t & 63;
    float acc = 0.f;
#pragma unroll
    for (int k = 0; k < 32; k++) acc = fmaf(xs[i * 32 + k], __ldg(&W[k * 64 + c]), acc);
    const int n = n0 + i;
    g_h3[(size_t)n * 64 + c] = acc;
    float e = wred(acc * al[c]);
    float r = wred(acc * ar[c]);
    const int warp = t >> 5, lane = t & 31;
    if (lane == 0) { sm_e[warp] = e; sm_r[warp] = r; }
    __syncthreads();
    if (t < 4) {
        g_el3[n0 + t] = sm_e[2 * t] + sm_e[2 * t + 1];
        g_er3[n0 + t] = sm_r[2 * t] + sm_r[2 * t + 1];
    }
}

// ---------------- layer 3 aggregation ----------------
__global__ void agg3_kernel(const float* __restrict__ b3, float* __restrict__ out) {
    const int wid = (blockIdx.x * blockDim.x + threadIdx.x) >> 5;
    const int lane = threadIdx.x & 31;
    if (wid >= Nn) return;
    const int d = wid;
    const int rs = g_rowstart[d], re = g_rowstart[d + 1];
    const float erd = g_er3[d];
    float acc0 = 0.f, acc1 = 0.f, s = 0.f;
    for (int e = rs; e < re; e++) {
        int src = g_esrc[e];
        float ee = __expf(lrelu(g_el3[src] + erd));
        s += ee;
        const float* hp = g_h3 + (size_t)src * 64;
        acc0 = fmaf(ee, hp[lane], acc0);
        acc1 = fmaf(ee, hp[32 + lane], acc1);
    }
    float inv = (s > 0.f) ? (1.f / s) : 0.f;
    out[(size_t)d * 64 + lane]      = acc0 * inv + b3[lane];
    out[(size_t)d * 64 + 32 + lane] = acc1 * inv + b3[32 + lane];
}

// ---------------- launch ----------------
extern "C" void kernel_launch(void* const* d_in, const int* in_sizes, int n_in,
                              void* d_out, int out_size) {
    const float* features = (const float*)d_in[0];
    const int*   src      = (const int*)d_in[1];
    const int*   dst      = (const int*)d_in[2];
    const float* W1  = (const float*)d_in[3];
    const float* al1 = (const float*)d_in[4];
    const float* ar1 = (const float*)d_in[5];
    const float* b1  = (const float*)d_in[6];
    const float* W2  = (const float*)d_in[7];
    const float* al2 = (const float*)d_in[8];
    const float* ar2 = (const float*)d_in[9];
    const float* b2  = (const float*)d_in[10];
    const float* W3  = (const float*)d_in[11];
    const float* al3 = (const float*)d_in[12];
    const float* ar3 = (const float*)d_in[13];
    const float* b3  = (const float*)d_in[14];

    float* out = (float*)d_out;                 // h: [N,64] first
    float* emb = out + (size_t)Nn * 64;         // embedding: [N,32] second

    static bool attr_set = false;
    if (!attr_set) {
        cudaFuncSetAttribute(gemm1m_kernel, cudaFuncAttributeMaxDynamicSharedMemorySize, G1_SMEM);
        attr_set = true;
    }

    // CSR build (graph identical across layers)
    zero_kernel<<<(Nn + 255) / 256, 256>>>();
    count_kernel<<<(Ne + 255) / 256, 256>>>(dst);
    scan_kernel<<<1, 1024>>>();
    scatter_kernel<<<(Ne + 255) / 256, 256>>>(src, dst);

    // layer 1
    wpack_kernel<<<128, 256>>>(W1);
    gemm1m_kernel<<<(Nn + 63) / 64, 256, G1_SMEM>>>(features);
    elr1_kernel<<<(Nn + 7) / 8, 256>>>(al1, ar1);
    agg1_kernel<<<Nn / 8, 256>>>(b1);
    // layer 2
    gemm2_kernel<<<Nn / 8, 256>>>(W2, al2, ar2);
    agg2_kernel<<<Nn / 8, 256>>>(b2, emb);
    // layer 3
    gemm3_kernel<<<Nn / 4, 256>>>(emb, W3, al3, ar3);
    agg3_kernel<<<Nn / 8, 256>>>(b3, out);
}